// round 1
// baseline (speedup 1.0000x reference)
#include <cuda_runtime.h>
#include <cuda_bf16.h>

#define N_CTX 4080
#define TPAD  4096
#define NS    1024
#define NH    16
#define DH    64

// ---------------- scratch (static device globals; no allocation) ----------------
__device__ __nv_bfloat16 g_rb[TPAD * NS];          // LN output, bf16, padded rows zero
__device__ __nv_bfloat16 g_wt[4][NS * NS];         // transposed bf16 weights: [n][k]
__device__ __nv_bfloat16 g_q[NH * TPAD * DH];      // [h][t][d]
__device__ __nv_bfloat16 g_k[NH * TPAD * DH];      // [h][t][d]
__device__ __nv_bfloat16 g_vt[NH * DH * TPAD];     // [h][d][t]  (transposed V)
__device__ __nv_bfloat16 g_att[TPAD * NS];         // attention output, [t][h*64+d]

// ---------------- mma helpers ----------------
__device__ __forceinline__ void mma16816(float c[4], const unsigned a[4], const unsigned b[2]) {
    asm volatile(
        "mma.sync.aligned.m16n8k16.row.col.f32.bf16.bf16.f32 "
        "{%0,%1,%2,%3}, {%4,%5,%6,%7}, {%8,%9}, {%0,%1,%2,%3};\n"
        : "+f"(c[0]), "+f"(c[1]), "+f"(c[2]), "+f"(c[3])
        : "r"(a[0]), "r"(a[1]), "r"(a[2]), "r"(a[3]), "r"(b[0]), "r"(b[1]));
}

__device__ __forceinline__ unsigned pack_bf16(float lo, float hi) {
    __nv_bfloat162 h = __floats2bfloat162_rn(lo, hi);
    return *reinterpret_cast<unsigned*>(&h);
}

// ---------------- weight transpose to bf16 ----------------
__global__ void transpose_w_kernel(const float* __restrict__ W, int widx) {
    __shared__ float tile[32][33];
    int tx = threadIdx.x, ty = threadIdx.y;
    int bx = blockIdx.x * 32, by = blockIdx.y * 32;   // bx: n, by: k
    tile[ty][tx] = W[(size_t)(by + ty) * NS + bx + tx];
    __syncthreads();
    g_wt[widx][(size_t)(bx + ty) * NS + by + tx] = __float2bfloat16(tile[tx][ty]);
}

// ---------------- layernorm ----------------
__global__ void ln_kernel(const float* __restrict__ m,
                          const float* __restrict__ gamma,
                          const float* __restrict__ beta) {
    int row = blockIdx.x;
    int tid = threadIdx.x;   // 256 threads
    if (row >= N_CTX) {
        unsigned* dst = (unsigned*)(g_rb + (size_t)row * NS);
        dst[tid] = 0u;
        dst[tid + 256] = 0u;
        return;
    }
    float4 x = ((const float4*)(m + (size_t)row * NS))[tid];
    float s  = x.x + x.y + x.z + x.w;
    float sq = x.x * x.x + x.y * x.y + x.z * x.z + x.w * x.w;
    #pragma unroll
    for (int o = 16; o > 0; o >>= 1) {
        s  += __shfl_xor_sync(0xffffffffu, s,  o);
        sq += __shfl_xor_sync(0xffffffffu, sq, o);
    }
    __shared__ float redS[8], redQ[8], bcast[2];
    int wid = tid >> 5, ln = tid & 31;
    if (ln == 0) { redS[wid] = s; redQ[wid] = sq; }
    __syncthreads();
    if (tid == 0) {
        float S = 0.f, Q = 0.f;
        #pragma unroll
        for (int i = 0; i < 8; i++) { S += redS[i]; Q += redQ[i]; }
        float mu  = S * (1.0f / NS);
        float var = Q * (1.0f / NS) - mu * mu;
        bcast[0] = mu;
        bcast[1] = rsqrtf(var + 1e-5f);
    }
    __syncthreads();
    float mu = bcast[0], rstd = bcast[1];
    float4 g = ((const float4*)gamma)[tid];
    float4 b = ((const float4*)beta)[tid];
    float y0 = (x.x - mu) * rstd * g.x + b.x;
    float y1 = (x.y - mu) * rstd * g.y + b.y;
    float y2 = (x.z - mu) * rstd * g.z + b.z;
    float y3 = (x.w - mu) * rstd * g.w + b.w;
    __nv_bfloat162* out = (__nv_bfloat162*)(g_rb + (size_t)row * NS);
    out[2 * tid]     = __floats2bfloat162_rn(y0, y1);
    out[2 * tid + 1] = __floats2bfloat162_rn(y2, y3);
}

// ---------------- generic 128x128x32 bf16 HMMA GEMM ----------------
// mode 0: q = r@Wq + bq  -> g_q [h][t][d]   (rows>=N_CTX forced 0)
// mode 1: k = r@Wk       -> g_k [h][t][d]   (rows>=N_CTX forced 0)
// mode 2: v = r@Wv + bv  -> g_vt [h][d][t]  (rows>=N_CTX forced 0)
// mode 3: out = m + att@Wc + bc (fp32, rows < N_CTX only)
__global__ void gemm_kernel(int mode, const float* __restrict__ bias,
                            const float* __restrict__ madd, float* __restrict__ out) {
    constexpr int LDS_ = 40;  // 32 + 8 pad
    __shared__ __nv_bfloat16 As[128 * LDS_];
    __shared__ __nv_bfloat16 Bs[128 * LDS_];

    const __nv_bfloat16* A  = (mode < 3) ? g_rb : g_att;
    const __nv_bfloat16* BT = g_wt[mode];

    int n0 = blockIdx.x * 128, t0 = blockIdx.y * 128;
    int tid = threadIdx.x;
    int wid = tid >> 5, lane = tid & 31, gid = lane >> 2, tig = lane & 3;
    int wm = wid & 1, wn = wid >> 1;

    float c[4][4][4];
    #pragma unroll
    for (int i = 0; i < 4; i++)
        #pragma unroll
        for (int j = 0; j < 4; j++)
            #pragma unroll
            for (int k = 0; k < 4; k++) c[i][j][k] = 0.f;

    for (int kt = 0; kt < 32; kt++) {
        int k0 = kt * 32;
        __syncthreads();
        #pragma unroll
        for (int i = 0; i < 2; i++) {
            int idx = tid + i * 256;          // 0..511
            int row = idx >> 2, cc = idx & 3;
            ((uint4*)As)[row * 5 + cc] = *(const uint4*)(A  + (size_t)(t0 + row) * NS + k0 + cc * 8);
            ((uint4*)Bs)[row * 5 + cc] = *(const uint4*)(BT + (size_t)(n0 + row) * NS + k0 + cc * 8);
        }
        __syncthreads();
        #pragma unroll
        for (int ks = 0; ks < 2; ks++) {
            unsigned a[4][4], b[4][2];
            #pragma unroll
            for (int mf = 0; mf < 4; mf++) {
                int r = wm * 64 + mf * 16 + gid;
                const __nv_bfloat16* p = As + r * LDS_ + ks * 16 + tig * 2;
                a[mf][0] = *(const unsigned*)p;
                a[mf][1] = *(const unsigned*)(p + 8 * LDS_);
                a[mf][2] = *(const unsigned*)(p + 8);
                a[mf][3] = *(const unsigned*)(p + 8 * LDS_ + 8);
            }
            #pragma unroll
            for (int nf = 0; nf < 4; nf++) {
                int cn = wn * 32 + nf * 8 + gid;
                const __nv_bfloat16* p = Bs + cn * LDS_ + ks * 16 + tig * 2;
                b[nf][0] = *(const unsigned*)p;
                b[nf][1] = *(const unsigned*)(p + 8);
            }
            #pragma unroll
            for (int mf = 0; mf < 4; mf++)
                #pragma unroll
                for (int nf = 0; nf < 4; nf++)
                    mma16816(c[mf][nf], a[mf], b[nf]);
        }
    }

    // ---------------- epilogue ----------------
    #pragma unroll
    for (int mf = 0; mf < 4; mf++) {
        #pragma unroll
        for (int nf = 0; nf < 4; nf++) {
            int r0 = t0 + wm * 64 + mf * 16 + gid;
            int cn = n0 + wn * 32 + nf * 8 + tig * 2;
            float* cc = c[mf][nf];
            if (mode == 3) {
                if (r0 < N_CTX) {
                    out[(size_t)r0 * NS + cn]     = madd[(size_t)r0 * NS + cn]     + cc[0] + bias[cn];
                    out[(size_t)r0 * NS + cn + 1] = madd[(size_t)r0 * NS + cn + 1] + cc[1] + bias[cn + 1];
                }
                if (r0 + 8 < N_CTX) {
                    out[(size_t)(r0 + 8) * NS + cn]     = madd[(size_t)(r0 + 8) * NS + cn]     + cc[2] + bias[cn];
                    out[(size_t)(r0 + 8) * NS + cn + 1] = madd[(size_t)(r0 + 8) * NS + cn + 1] + cc[3] + bias[cn + 1];
                }
            } else {
                float b0 = bias ? bias[cn] : 0.f;
                float b1 = bias ? bias[cn + 1] : 0.f;
                float v0 = (r0     < N_CTX) ? cc[0] + b0 : 0.f;
                float v1 = (r0     < N_CTX) ? cc[1] + b1 : 0.f;
                float v2 = (r0 + 8 < N_CTX) ? cc[2] + b0 : 0.f;
                float v3 = (r0 + 8 < N_CTX) ? cc[3] + b1 : 0.f;
                int head = cn >> 6, d = cn & 63;
                if (mode == 2) {
                    __nv_bfloat16* p0 = g_vt + ((size_t)head * DH + d) * TPAD;
                    __nv_bfloat16* p1 = p0 + TPAD;
                    p0[r0]     = __float2bfloat16(v0);
                    p0[r0 + 8] = __float2bfloat16(v2);
                    p1[r0]     = __float2bfloat16(v1);
                    p1[r0 + 8] = __float2bfloat16(v3);
                } else {
                    __nv_bfloat16* base = (mode == 0 ? g_q : g_k);
                    __nv_bfloat16* d0 = base + ((size_t)head * TPAD + r0) * DH + d;
                    d0[0] = __float2bfloat16(v0);
                    d0[1] = __float2bfloat16(v1);
                    __nv_bfloat16* d1 = d0 + 8 * DH;
                    d1[0] = __float2bfloat16(v2);
                    d1[1] = __float2bfloat16(v3);
                }
            }
        }
    }
}

// ---------------- flash attention (per head, 64-row q tile) ----------------
__global__ void attn_kernel(const float* __restrict__ bias) {
    constexpr int LP = 72;  // 64 + 8 pad
    __shared__ __nv_bfloat16 Qs[64 * LP];
    __shared__ __nv_bfloat16 Ks[64 * LP];
    __shared__ __nv_bfloat16 Vts[64 * LP];

    int head = blockIdx.x;   // fast dim -> heads co-scheduled, bias L2 reuse
    int qt   = blockIdx.y;
    int q0   = qt * 64;
    int tid = threadIdx.x, wid = tid >> 5, lane = tid & 31, gid = lane >> 2, tig = lane & 3;

    const __nv_bfloat16* gq = g_q + (size_t)head * TPAD * DH;
    const __nv_bfloat16* gk = g_k + (size_t)head * TPAD * DH;
    const __nv_bfloat16* gv = g_vt + (size_t)head * DH * TPAD;

    #pragma unroll
    for (int i = 0; i < 4; i++) {
        int idx = tid + i * 128;           // 0..511 chunks of 8 bf16
        int row = idx >> 3, cc = idx & 7;
        ((uint4*)Qs)[row * 9 + cc] = *(const uint4*)(gq + (size_t)(q0 + row) * DH + cc * 8);
    }

    float oacc[8][4];
    #pragma unroll
    for (int j = 0; j < 8; j++)
        #pragma unroll
        for (int i = 0; i < 4; i++) oacc[j][i] = 0.f;
    float mr0 = -1e30f, mr1 = -1e30f, l0 = 0.f, l1 = 0.f;
    int qrow = q0 + wid * 16 + gid;
    const float scale = 0.125f;

    for (int kt = 0; kt < 64; kt++) {
        int k0 = kt * 64;
        __syncthreads();
        #pragma unroll
        for (int i = 0; i < 4; i++) {
            int idx = tid + i * 128;
            int row = idx >> 3, cc = idx & 7;
            ((uint4*)Ks)[row * 9 + cc]  = *(const uint4*)(gk + (size_t)(k0 + row) * DH + cc * 8);
            ((uint4*)Vts)[row * 9 + cc] = *(const uint4*)(gv + (size_t)row * TPAD + k0 + cc * 8);
        }
        __syncthreads();

        float s[8][4];
        #pragma unroll
        for (int j = 0; j < 8; j++)
            #pragma unroll
            for (int i = 0; i < 4; i++) s[j][i] = 0.f;

        #pragma unroll
        for (int ks = 0; ks < 4; ks++) {
            unsigned a[4];
            const __nv_bfloat16* qp = Qs + (wid * 16 + gid) * LP + ks * 16 + tig * 2;
            a[0] = *(const unsigned*)qp;
            a[1] = *(const unsigned*)(qp + 8 * LP);
            a[2] = *(const unsigned*)(qp + 8);
            a[3] = *(const unsigned*)(qp + 8 * LP + 8);
            #pragma unroll
            for (int j = 0; j < 8; j++) {
                unsigned b[2];
                const __nv_bfloat16* kp = Ks + (j * 8 + gid) * LP + ks * 16 + tig * 2;
                b[0] = *(const unsigned*)kp;
                b[1] = *(const unsigned*)(kp + 8);
                mma16816(s[j], a, b);
            }
        }

        // logits = s*scale + bias ; online softmax
        float rm0 = -1e30f, rm1 = -1e30f;
        #pragma unroll
        for (int j = 0; j < 8; j++) {
            int col = k0 + j * 8 + tig * 2;
            const float* bp0 = bias + (size_t)qrow * TPAD + col;
            const float* bp1 = bias + (size_t)(qrow + 8) * TPAD + col;
            s[j][0] = s[j][0] * scale + bp0[0];
            s[j][1] = s[j][1] * scale + bp0[1];
            s[j][2] = s[j][2] * scale + bp1[0];
            s[j][3] = s[j][3] * scale + bp1[1];
            rm0 = fmaxf(rm0, fmaxf(s[j][0], s[j][1]));
            rm1 = fmaxf(rm1, fmaxf(s[j][2], s[j][3]));
        }
        rm0 = fmaxf(rm0, __shfl_xor_sync(0xffffffffu, rm0, 1));
        rm0 = fmaxf(rm0, __shfl_xor_sync(0xffffffffu, rm0, 2));
        rm1 = fmaxf(rm1, __shfl_xor_sync(0xffffffffu, rm1, 1));
        rm1 = fmaxf(rm1, __shfl_xor_sync(0xffffffffu, rm1, 2));
        float mn0 = fmaxf(mr0, rm0), mn1 = fmaxf(mr1, rm1);
        float al0 = __expf(mr0 - mn0), al1 = __expf(mr1 - mn1);

        float rs0 = 0.f, rs1 = 0.f;
        #pragma unroll
        for (int j = 0; j < 8; j++) {
            s[j][0] = __expf(s[j][0] - mn0);
            s[j][1] = __expf(s[j][1] - mn0);
            s[j][2] = __expf(s[j][2] - mn1);
            s[j][3] = __expf(s[j][3] - mn1);
            rs0 += s[j][0] + s[j][1];
            rs1 += s[j][2] + s[j][3];
        }
        rs0 += __shfl_xor_sync(0xffffffffu, rs0, 1);
        rs0 += __shfl_xor_sync(0xffffffffu, rs0, 2);
        rs1 += __shfl_xor_sync(0xffffffffu, rs1, 1);
        rs1 += __shfl_xor_sync(0xffffffffu, rs1, 2);
        l0 = l0 * al0 + rs0;
        l1 = l1 * al1 + rs1;
        mr0 = mn0; mr1 = mn1;
        #pragma unroll
        for (int j = 0; j < 8; j++) {
            oacc[j][0] *= al0; oacc[j][1] *= al0;
            oacc[j][2] *= al1; oacc[j][3] *= al1;
        }

        // O += P @ V  (C-fragment -> A-fragment register reuse)
        #pragma unroll
        for (int kk = 0; kk < 4; kk++) {
            unsigned a[4];
            a[0] = pack_bf16(s[2 * kk][0],     s[2 * kk][1]);
            a[1] = pack_bf16(s[2 * kk][2],     s[2 * kk][3]);
            a[2] = pack_bf16(s[2 * kk + 1][0], s[2 * kk + 1][1]);
            a[3] = pack_bf16(s[2 * kk + 1][2], s[2 * kk + 1][3]);
            #pragma unroll
            for (int j = 0; j < 8; j++) {
                unsigned b[2];
                const __nv_bfloat16* vp = Vts + (j * 8 + gid) * LP + kk * 16 + tig * 2;
                b[0] = *(const unsigned*)vp;
                b[1] = *(const unsigned*)(vp + 8);
                mma16816(oacc[j], a, b);
            }
        }
    }

    float inv0 = 1.f / l0, inv1 = 1.f / l1;
    #pragma unroll
    for (int j = 0; j < 8; j++) {
        int col = head * DH + j * 8 + tig * 2;
        __nv_bfloat16* d0 = g_att + (size_t)qrow * NS + col;
        __nv_bfloat16* d1 = g_att + (size_t)(qrow + 8) * NS + col;
        d0[0] = __float2bfloat16(oacc[j][0] * inv0);
        d0[1] = __float2bfloat16(oacc[j][1] * inv0);
        d1[0] = __float2bfloat16(oacc[j][2] * inv1);
        d1[1] = __float2bfloat16(oacc[j][3] * inv1);
    }
}

// ---------------- launch ----------------
extern "C" void kernel_launch(void* const* d_in, const int* in_sizes, int n_in,
                              void* d_out, int out_size) {
    const float* m     = (const float*)d_in[0];
    const float* bias  = (const float*)d_in[1];
    const float* gamma = (const float*)d_in[2];
    const float* beta  = (const float*)d_in[3];
    const float* Wq    = (const float*)d_in[4];
    const float* bq    = (const float*)d_in[5];
    const float* Wk    = (const float*)d_in[6];
    const float* Wv    = (const float*)d_in[7];
    const float* bv    = (const float*)d_in[8];
    const float* Wc    = (const float*)d_in[9];
    const float* bc    = (const float*)d_in[10];
    float* out = (float*)d_out;

    dim3 tb(32, 32), tg(32, 32);
    transpose_w_kernel<<<tg, tb>>>(Wq, 0);
    transpose_w_kernel<<<tg, tb>>>(Wk, 1);
    transpose_w_kernel<<<tg, tb>>>(Wv, 2);
    transpose_w_kernel<<<tg, tb>>>(Wc, 3);

    ln_kernel<<<TPAD, 256>>>(m, gamma, beta);

    dim3 gg(8, 32);
    gemm_kernel<<<gg, 256>>>(0, bq, nullptr, nullptr);
    gemm_kernel<<<gg, 256>>>(1, nullptr, nullptr, nullptr);
    gemm_kernel<<<gg, 256>>>(2, bv, nullptr, nullptr);

    attn_kernel<<<dim3(NH, TPAD / 64), 128>>>(bias);

    gemm_kernel<<<gg, 256>>>(3, bc, m, out);
}

// round 2
// speedup vs baseline: 1.3416x; 1.3416x over previous
#include <cuda_runtime.h>
#include <cuda_bf16.h>

#define N_CTX 4080
#define TPAD  4096
#define NS    1024
#define NH    16
#define DH    64

// ---------------- scratch (static device globals; no allocation) ----------------
__device__ __nv_bfloat16 g_rb[TPAD * NS];          // LN output, bf16, padded rows zero
__device__ __nv_bfloat16 g_wt[4][NS * NS];         // transposed bf16 weights: [n][k]
__device__ __nv_bfloat16 g_q[NH * TPAD * DH];      // [h][t][d]
__device__ __nv_bfloat16 g_k[NH * TPAD * DH];      // [h][t][d]
__device__ __nv_bfloat16 g_vt[NH * DH * TPAD];     // [h][d][t]  (transposed V)
__device__ __nv_bfloat16 g_att[TPAD * NS];         // attention output, [t][h*64+d]
__device__ __nv_bfloat16 g_biasb[(size_t)TPAD * TPAD]; // bias in bf16

// ---------------- helpers ----------------
__device__ __forceinline__ void mma16816(float c[4], const unsigned a[4], const unsigned b[2]) {
    asm volatile(
        "mma.sync.aligned.m16n8k16.row.col.f32.bf16.bf16.f32 "
        "{%0,%1,%2,%3}, {%4,%5,%6,%7}, {%8,%9}, {%0,%1,%2,%3};\n"
        : "+f"(c[0]), "+f"(c[1]), "+f"(c[2]), "+f"(c[3])
        : "r"(a[0]), "r"(a[1]), "r"(a[2]), "r"(a[3]), "r"(b[0]), "r"(b[1]));
}

__device__ __forceinline__ unsigned pack_bf16(float lo, float hi) {
    __nv_bfloat162 h = __floats2bfloat162_rn(lo, hi);
    return *reinterpret_cast<unsigned*>(&h);
}

__device__ __forceinline__ void cpa16(void* dst, const void* src) {
    unsigned a = (unsigned)__cvta_generic_to_shared(dst);
    asm volatile("cp.async.cg.shared.global [%0], [%1], 16;\n" :: "r"(a), "l"(src));
}
__device__ __forceinline__ void cp_commit() { asm volatile("cp.async.commit_group;\n" ::); }
__device__ __forceinline__ void cp_wait1()  { asm volatile("cp.async.wait_group 1;\n" ::); }
__device__ __forceinline__ void cp_wait0()  { asm volatile("cp.async.wait_group 0;\n" ::); }

// ---------------- weight transpose (all 4 fused) ----------------
__global__ void transpose_w_kernel(const float* __restrict__ Wq, const float* __restrict__ Wk,
                                   const float* __restrict__ Wv, const float* __restrict__ Wc) {
    __shared__ float tile[32][33];
    const float* W = (blockIdx.z == 0) ? Wq : (blockIdx.z == 1) ? Wk : (blockIdx.z == 2) ? Wv : Wc;
    int tx = threadIdx.x, ty = threadIdx.y;
    int bx = blockIdx.x * 32, by = blockIdx.y * 32;   // bx: n, by: k
    tile[ty][tx] = W[(size_t)(by + ty) * NS + bx + tx];
    __syncthreads();
    g_wt[blockIdx.z][(size_t)(bx + ty) * NS + by + tx] = __float2bfloat16(tile[tx][ty]);
}

// ---------------- bias fp32 -> bf16 ----------------
__global__ void biasconv_kernel(const float* __restrict__ bias) {
    size_t i = ((size_t)blockIdx.x * 256 + threadIdx.x) * 4;
    float4 v = *(const float4*)(bias + i);
    __nv_bfloat162* o = (__nv_bfloat162*)(g_biasb + i);
    o[0] = __floats2bfloat162_rn(v.x, v.y);
    o[1] = __floats2bfloat162_rn(v.z, v.w);
}

// ---------------- layernorm ----------------
__global__ void ln_kernel(const float* __restrict__ m,
                          const float* __restrict__ gamma,
                          const float* __restrict__ beta) {
    int row = blockIdx.x;
    int tid = threadIdx.x;   // 256 threads
    if (row >= N_CTX) {
        unsigned* dst = (unsigned*)(g_rb + (size_t)row * NS);
        dst[tid] = 0u;
        dst[tid + 256] = 0u;
        return;
    }
    float4 x = ((const float4*)(m + (size_t)row * NS))[tid];
    float s  = x.x + x.y + x.z + x.w;
    float sq = x.x * x.x + x.y * x.y + x.z * x.z + x.w * x.w;
    #pragma unroll
    for (int o = 16; o > 0; o >>= 1) {
        s  += __shfl_xor_sync(0xffffffffu, s,  o);
        sq += __shfl_xor_sync(0xffffffffu, sq, o);
    }
    __shared__ float redS[8], redQ[8], bcast[2];
    int wid = tid >> 5, ln = tid & 31;
    if (ln == 0) { redS[wid] = s; redQ[wid] = sq; }
    __syncthreads();
    if (tid == 0) {
        float S = 0.f, Q = 0.f;
        #pragma unroll
        for (int i = 0; i < 8; i++) { S += redS[i]; Q += redQ[i]; }
        float mu  = S * (1.0f / NS);
        float var = Q * (1.0f / NS) - mu * mu;
        bcast[0] = mu;
        bcast[1] = rsqrtf(var + 1e-5f);
    }
    __syncthreads();
    float mu = bcast[0], rstd = bcast[1];
    float4 g = ((const float4*)gamma)[tid];
    float4 b = ((const float4*)beta)[tid];
    float y0 = (x.x - mu) * rstd * g.x + b.x;
    float y1 = (x.y - mu) * rstd * g.y + b.y;
    float y2 = (x.z - mu) * rstd * g.z + b.z;
    float y3 = (x.w - mu) * rstd * g.w + b.w;
    __nv_bfloat162* out = (__nv_bfloat162*)(g_rb + (size_t)row * NS);
    out[2 * tid]     = __floats2bfloat162_rn(y0, y1);
    out[2 * tid + 1] = __floats2bfloat162_rn(y2, y3);
}

// ======================= fused QKV GEMM (double-buffered) =======================
// grid (24, 32): gn in [0,3072) -> mode = gn>>10 (0:Q,1:K,2:V), n0 = gn & 1023.
__global__ __launch_bounds__(256, 2) void gemm_qkv_kernel(const float* __restrict__ bq,
                                                          const float* __restrict__ bv) {
    constexpr int LDS_ = 40;  // 32 + 8 pad
    __shared__ __nv_bfloat16 As[2][128 * LDS_];
    __shared__ __nv_bfloat16 Bs[2][128 * LDS_];

    int gn0 = blockIdx.x * 128;
    int mode = gn0 >> 10;
    int n0 = gn0 & 1023;
    int t0 = blockIdx.y * 128;
    const __nv_bfloat16* A  = g_rb;
    const __nv_bfloat16* BT = g_wt[mode];

    int tid = threadIdx.x;
    int wid = tid >> 5, lane = tid & 31, gid = lane >> 2, tig = lane & 3;
    int wm = wid & 1, wn = wid >> 1;

    float c[4][4][4];
    #pragma unroll
    for (int i = 0; i < 4; i++)
        #pragma unroll
        for (int j = 0; j < 4; j++)
            #pragma unroll
            for (int k = 0; k < 4; k++) c[i][j][k] = 0.f;

    auto issue = [&](int kt) {
        int buf = kt & 1, k0 = kt * 32;
        #pragma unroll
        for (int i = 0; i < 2; i++) {
            int idx = tid + i * 256;            // 0..511
            int row = idx >> 2, cc = idx & 3;
            cpa16(&((uint4*)As[buf])[row * 5 + cc], A  + (size_t)(t0 + row) * NS + k0 + cc * 8);
            cpa16(&((uint4*)Bs[buf])[row * 5 + cc], BT + (size_t)(n0 + row) * NS + k0 + cc * 8);
        }
        cp_commit();
    };

    issue(0);
    for (int kt = 0; kt < 32; kt++) {
        if (kt < 31) { issue(kt + 1); cp_wait1(); } else cp_wait0();
        __syncthreads();
        int buf = kt & 1;
        #pragma unroll
        for (int ks = 0; ks < 2; ks++) {
            unsigned a[4][4], b[4][2];
            #pragma unroll
            for (int mf = 0; mf < 4; mf++) {
                int r = wm * 64 + mf * 16 + gid;
                const __nv_bfloat16* p = As[buf] + r * LDS_ + ks * 16 + tig * 2;
                a[mf][0] = *(const unsigned*)p;
                a[mf][1] = *(const unsigned*)(p + 8 * LDS_);
                a[mf][2] = *(const unsigned*)(p + 8);
                a[mf][3] = *(const unsigned*)(p + 8 * LDS_ + 8);
            }
            #pragma unroll
            for (int nf = 0; nf < 4; nf++) {
                int cn = wn * 32 + nf * 8 + gid;
                const __nv_bfloat16* p = Bs[buf] + cn * LDS_ + ks * 16 + tig * 2;
                b[nf][0] = *(const unsigned*)p;
                b[nf][1] = *(const unsigned*)(p + 8);
            }
            #pragma unroll
            for (int mf = 0; mf < 4; mf++)
                #pragma unroll
                for (int nf = 0; nf < 4; nf++)
                    mma16816(c[mf][nf], a[mf], b[nf]);
        }
        __syncthreads();
    }

    // epilogue -> q/k [h][t][d], v [h][d][t]; rows >= N_CTX zeroed
    #pragma unroll
    for (int mf = 0; mf < 4; mf++) {
        #pragma unroll
        for (int nf = 0; nf < 4; nf++) {
            int r0 = t0 + wm * 64 + mf * 16 + gid;
            int cn = n0 + wn * 32 + nf * 8 + tig * 2;
            float* cc = c[mf][nf];
            const float* bias = (mode == 0) ? bq : (mode == 2) ? bv : nullptr;
            float b0 = bias ? bias[cn] : 0.f;
            float b1 = bias ? bias[cn + 1] : 0.f;
            float v0 = (r0     < N_CTX) ? cc[0] + b0 : 0.f;
            float v1 = (r0     < N_CTX) ? cc[1] + b1 : 0.f;
            float v2 = (r0 + 8 < N_CTX) ? cc[2] + b0 : 0.f;
            float v3 = (r0 + 8 < N_CTX) ? cc[3] + b1 : 0.f;
            int head = cn >> 6, d = cn & 63;
            if (mode == 2) {
                __nv_bfloat16* p0 = g_vt + ((size_t)head * DH + d) * TPAD;
                __nv_bfloat16* p1 = p0 + TPAD;
                p0[r0]     = __float2bfloat16(v0);
                p0[r0 + 8] = __float2bfloat16(v2);
                p1[r0]     = __float2bfloat16(v1);
                p1[r0 + 8] = __float2bfloat16(v3);
            } else {
                __nv_bfloat16* base = (mode == 0 ? g_q : g_k);
                __nv_bfloat16* d0 = base + ((size_t)head * TPAD + r0) * DH + d;
                d0[0] = __float2bfloat16(v0);
                d0[1] = __float2bfloat16(v1);
                __nv_bfloat16* d1 = d0 + 8 * DH;
                d1[0] = __float2bfloat16(v2);
                d1[1] = __float2bfloat16(v3);
            }
        }
    }
}

// ======================= output GEMM (double-buffered) =======================
__global__ __launch_bounds__(256, 2) void gemm_out_kernel(const float* __restrict__ bc,
                                                          const float* __restrict__ madd,
                                                          float* __restrict__ out) {
    constexpr int LDS_ = 40;
    __shared__ __nv_bfloat16 As[2][128 * LDS_];
    __shared__ __nv_bfloat16 Bs[2][128 * LDS_];

    int n0 = blockIdx.x * 128, t0 = blockIdx.y * 128;
    const __nv_bfloat16* A  = g_att;
    const __nv_bfloat16* BT = g_wt[3];

    int tid = threadIdx.x;
    int wid = tid >> 5, lane = tid & 31, gid = lane >> 2, tig = lane & 3;
    int wm = wid & 1, wn = wid >> 1;

    float c[4][4][4];
    #pragma unroll
    for (int i = 0; i < 4; i++)
        #pragma unroll
        for (int j = 0; j < 4; j++)
            #pragma unroll
            for (int k = 0; k < 4; k++) c[i][j][k] = 0.f;

    auto issue = [&](int kt) {
        int buf = kt & 1, k0 = kt * 32;
        #pragma unroll
        for (int i = 0; i < 2; i++) {
            int idx = tid + i * 256;
            int row = idx >> 2, cc = idx & 3;
            cpa16(&((uint4*)As[buf])[row * 5 + cc], A  + (size_t)(t0 + row) * NS + k0 + cc * 8);
            cpa16(&((uint4*)Bs[buf])[row * 5 + cc], BT + (size_t)(n0 + row) * NS + k0 + cc * 8);
        }
        cp_commit();
    };

    issue(0);
    for (int kt = 0; kt < 32; kt++) {
        if (kt < 31) { issue(kt + 1); cp_wait1(); } else cp_wait0();
        __syncthreads();
        int buf = kt & 1;
        #pragma unroll
        for (int ks = 0; ks < 2; ks++) {
            unsigned a[4][4], b[4][2];
            #pragma unroll
            for (int mf = 0; mf < 4; mf++) {
                int r = wm * 64 + mf * 16 + gid;
                const __nv_bfloat16* p = As[buf] + r * LDS_ + ks * 16 + tig * 2;
                a[mf][0] = *(const unsigned*)p;
                a[mf][1] = *(const unsigned*)(p + 8 * LDS_);
                a[mf][2] = *(const unsigned*)(p + 8);
                a[mf][3] = *(const unsigned*)(p + 8 * LDS_ + 8);
            }
            #pragma unroll
            for (int nf = 0; nf < 4; nf++) {
                int cn = wn * 32 + nf * 8 + gid;
                const __nv_bfloat16* p = Bs[buf] + cn * LDS_ + ks * 16 + tig * 2;
                b[nf][0] = *(const unsigned*)p;
                b[nf][1] = *(const unsigned*)(p + 8);
            }
            #pragma unroll
            for (int mf = 0; mf < 4; mf++)
                #pragma unroll
                for (int nf = 0; nf < 4; nf++)
                    mma16816(c[mf][nf], a[mf], b[nf]);
        }
        __syncthreads();
    }

    #pragma unroll
    for (int mf = 0; mf < 4; mf++) {
        #pragma unroll
        for (int nf = 0; nf < 4; nf++) {
            int r0 = t0 + wm * 64 + mf * 16 + gid;
            int cn = n0 + wn * 32 + nf * 8 + tig * 2;
            float* cc = c[mf][nf];
            if (r0 < N_CTX) {
                out[(size_t)r0 * NS + cn]     = madd[(size_t)r0 * NS + cn]     + cc[0] + bc[cn];
                out[(size_t)r0 * NS + cn + 1] = madd[(size_t)r0 * NS + cn + 1] + cc[1] + bc[cn + 1];
            }
            if (r0 + 8 < N_CTX) {
                out[(size_t)(r0 + 8) * NS + cn]     = madd[(size_t)(r0 + 8) * NS + cn]     + cc[2] + bc[cn];
                out[(size_t)(r0 + 8) * NS + cn + 1] = madd[(size_t)(r0 + 8) * NS + cn + 1] + cc[3] + bc[cn + 1];
            }
        }
    }
}

// ======================= flash attention: 128-row q tile, 8 warps, pipelined =======================
#define ATTN_LP   72
#define ATTN_SMEM ((128 + 2*64 + 2*64 + 2*128) * ATTN_LP * 2)   // 92160 bytes

__global__ __launch_bounds__(256, 1) void attn_kernel() {
    constexpr int LP = ATTN_LP;
    extern __shared__ __nv_bfloat16 sm[];
    __nv_bfloat16* Qs = sm;                       // 128*LP
    __nv_bfloat16* Ks = Qs + 128 * LP;            // 2 * 64*LP
    __nv_bfloat16* Vt = Ks + 2 * 64 * LP;         // 2 * 64*LP
    __nv_bfloat16* Bb = Vt + 2 * 64 * LP;         // 2 * 128*LP

    int head = blockIdx.x;    // fast dim -> 16 heads of same q-tile co-resident, bias L2 reuse
    int q0   = blockIdx.y * 128;
    int tid = threadIdx.x, wid = tid >> 5, lane = tid & 31, gid = lane >> 2, tig = lane & 3;

    const __nv_bfloat16* gq = g_q  + (size_t)head * TPAD * DH;
    const __nv_bfloat16* gk = g_k  + (size_t)head * TPAD * DH;
    const __nv_bfloat16* gv = g_vt + (size_t)head * DH * TPAD;

    auto issue = [&](int kt) {
        int buf = kt & 1, k0 = kt * 64;
        __nv_bfloat16* kd = Ks + buf * 64 * LP;
        __nv_bfloat16* vd = Vt + buf * 64 * LP;
        __nv_bfloat16* bd = Bb + buf * 128 * LP;
        #pragma unroll
        for (int i = 0; i < 2; i++) {
            int idx = tid + i * 256;              // 0..511
            int row = idx >> 3, cc = idx & 7;
            cpa16(&((uint4*)kd)[row * 9 + cc], gk + (size_t)(k0 + row) * DH + cc * 8);
            cpa16(&((uint4*)vd)[row * 9 + cc], gv + (size_t)row * TPAD + k0 + cc * 8);
        }
        #pragma unroll
        for (int i = 0; i < 4; i++) {
            int idx = tid + i * 256;              // 0..1023
            int row = idx >> 3, cc = idx & 7;
            cpa16(&((uint4*)bd)[row * 9 + cc], g_biasb + (size_t)(q0 + row) * TPAD + k0 + cc * 8);
        }
        cp_commit();
    };

    issue(0);
    // Q tile via regular loads (overlaps with first cp.async group)
    #pragma unroll
    for (int i = 0; i < 4; i++) {
        int idx = tid + i * 256;
        int row = idx >> 3, cc = idx & 7;
        ((uint4*)Qs)[row * 9 + cc] = *(const uint4*)(gq + (size_t)(q0 + row) * DH + cc * 8);
    }

    float oacc[8][4];
    #pragma unroll
    for (int j = 0; j < 8; j++)
        #pragma unroll
        for (int i = 0; i < 4; i++) oacc[j][i] = 0.f;
    float mr0 = -1e30f, mr1 = -1e30f, l0 = 0.f, l1 = 0.f;
    int qrow = q0 + wid * 16 + gid;
    const float scale = 0.125f;

    for (int kt = 0; kt < 64; kt++) {
        if (kt < 63) { issue(kt + 1); cp_wait1(); } else cp_wait0();
        __syncthreads();
        int buf = kt & 1;
        const __nv_bfloat16* kd = Ks + buf * 64 * LP;
        const __nv_bfloat16* vd = Vt + buf * 64 * LP;
        const __nv_bfloat16* bd = Bb + buf * 128 * LP;

        float s[8][4];
        #pragma unroll
        for (int j = 0; j < 8; j++)
            #pragma unroll
            for (int i = 0; i < 4; i++) s[j][i] = 0.f;

        #pragma unroll
        for (int ks = 0; ks < 4; ks++) {
            unsigned a[4];
            const __nv_bfloat16* qp = Qs + (wid * 16 + gid) * LP + ks * 16 + tig * 2;
            a[0] = *(const unsigned*)qp;
            a[1] = *(const unsigned*)(qp + 8 * LP);
            a[2] = *(const unsigned*)(qp + 8);
            a[3] = *(const unsigned*)(qp + 8 * LP + 8);
            #pragma unroll
            for (int j = 0; j < 8; j++) {
                unsigned b[2];
                const __nv_bfloat16* kp = kd + (j * 8 + gid) * LP + ks * 16 + tig * 2;
                b[0] = *(const unsigned*)kp;
                b[1] = *(const unsigned*)(kp + 8);
                mma16816(s[j], a, b);
            }
        }

        // logits = s*scale + bias ; online softmax (bias from smem, bf16)
        const __nv_bfloat16* br0 = bd + (wid * 16 + gid) * LP;
        const __nv_bfloat16* br1 = br0 + 8 * LP;
        float rm0 = -1e30f, rm1 = -1e30f;
        #pragma unroll
        for (int j = 0; j < 8; j++) {
            float2 b0 = __bfloat1622float2(*(const __nv_bfloat162*)(br0 + j * 8 + tig * 2));
            float2 b1 = __bfloat1622float2(*(const __nv_bfloat162*)(br1 + j * 8 + tig * 2));
            s[j][0] = s[j][0] * scale + b0.x;
            s[j][1] = s[j][1] * scale + b0.y;
            s[j][2] = s[j][2] * scale + b1.x;
            s[j][3] = s[j][3] * scale + b1.y;
            rm0 = fmaxf(rm0, fmaxf(s[j][0], s[j][1]));
            rm1 = fmaxf(rm1, fmaxf(s[j][2], s[j][3]));
        }
        rm0 = fmaxf(rm0, __shfl_xor_sync(0xffffffffu, rm0, 1));
        rm0 = fmaxf(rm0, __shfl_xor_sync(0xffffffffu, rm0, 2));
        rm1 = fmaxf(rm1, __shfl_xor_sync(0xffffffffu, rm1, 1));
        rm1 = fmaxf(rm1, __shfl_xor_sync(0xffffffffu, rm1, 2));
        float mn0 = fmaxf(mr0, rm0), mn1 = fmaxf(mr1, rm1);
        float al0 = __expf(mr0 - mn0), al1 = __expf(mr1 - mn1);

        float rs0 = 0.f, rs1 = 0.f;
        #pragma unroll
        for (int j = 0; j < 8; j++) {
            s[j][0] = __expf(s[j][0] - mn0);
            s[j][1] = __expf(s[j][1] - mn0);
            s[j][2] = __expf(s[j][2] - mn1);
            s[j][3] = __expf(s[j][3] - mn1);
            rs0 += s[j][0] + s[j][1];
            rs1 += s[j][2] + s[j][3];
        }
        rs0 += __shfl_xor_sync(0xffffffffu, rs0, 1);
        rs0 += __shfl_xor_sync(0xffffffffu, rs0, 2);
        rs1 += __shfl_xor_sync(0xffffffffu, rs1, 1);
        rs1 += __shfl_xor_sync(0xffffffffu, rs1, 2);
        l0 = l0 * al0 + rs0;
        l1 = l1 * al1 + rs1;
        mr0 = mn0; mr1 = mn1;
        #pragma unroll
        for (int j = 0; j < 8; j++) {
            oacc[j][0] *= al0; oacc[j][1] *= al0;
            oacc[j][2] *= al1; oacc[j][3] *= al1;
        }

        // O += P @ V  (C-fragment -> A-fragment register reuse)
        #pragma unroll
        for (int kk = 0; kk < 4; kk++) {
            unsigned a[4];
            a[0] = pack_bf16(s[2 * kk][0],     s[2 * kk][1]);
            a[1] = pack_bf16(s[2 * kk][2],     s[2 * kk][3]);
            a[2] = pack_bf16(s[2 * kk + 1][0], s[2 * kk + 1][1]);
            a[3] = pack_bf16(s[2 * kk + 1][2], s[2 * kk + 1][3]);
            #pragma unroll
            for (int j = 0; j < 8; j++) {
                unsigned b[2];
                const __nv_bfloat16* vp = vd + (j * 8 + gid) * LP + kk * 16 + tig * 2;
                b[0] = *(const unsigned*)vp;
                b[1] = *(const unsigned*)(vp + 8);
                mma16816(oacc[j], a, b);
            }
        }
        __syncthreads();
    }

    float inv0 = 1.f / l0, inv1 = 1.f / l1;
    #pragma unroll
    for (int j = 0; j < 8; j++) {
        int col = head * DH + j * 8 + tig * 2;
        __nv_bfloat16* d0 = g_att + (size_t)qrow * NS + col;
        __nv_bfloat16* d1 = g_att + (size_t)(qrow + 8) * NS + col;
        d0[0] = __float2bfloat16(oacc[j][0] * inv0);
        d0[1] = __float2bfloat16(oacc[j][1] * inv0);
        d1[0] = __float2bfloat16(oacc[j][2] * inv1);
        d1[1] = __float2bfloat16(oacc[j][3] * inv1);
    }
}

// ---------------- launch ----------------
extern "C" void kernel_launch(void* const* d_in, const int* in_sizes, int n_in,
                              void* d_out, int out_size) {
    const float* m     = (const float*)d_in[0];
    const float* bias  = (const float*)d_in[1];
    const float* gamma = (const float*)d_in[2];
    const float* beta  = (const float*)d_in[3];
    const float* Wq    = (const float*)d_in[4];
    const float* bq    = (const float*)d_in[5];
    const float* Wk    = (const float*)d_in[6];
    const float* Wv    = (const float*)d_in[7];
    const float* bv    = (const float*)d_in[8];
    const float* Wc    = (const float*)d_in[9];
    const float* bc    = (const float*)d_in[10];
    float* out = (float*)d_out;

    transpose_w_kernel<<<dim3(32, 32, 4), dim3(32, 32)>>>(Wq, Wk, Wv, Wc);
    biasconv_kernel<<<(TPAD * TPAD) / (256 * 4), 256>>>(bias);
    ln_kernel<<<TPAD, 256>>>(m, gamma, beta);

    gemm_qkv_kernel<<<dim3(24, 32), 256>>>(bq, bv);

    cudaFuncSetAttribute(attn_kernel, cudaFuncAttributeMaxDynamicSharedMemorySize, ATTN_SMEM);
    attn_kernel<<<dim3(NH, TPAD / 128), 256, ATTN_SMEM>>>();

    gemm_out_kernel<<<dim3(8, 32), 256>>>(bc, m, out);
}

// round 3
// speedup vs baseline: 1.3442x; 1.0019x over previous
#include <cuda_runtime.h>
#include <cuda_bf16.h>

#define N_CTX 4080
#define TPAD  4096
#define NS    1024
#define NH    16
#define DH    64

#define LOG2E 1.4426950408889634f
#define QSCALE (0.125f * LOG2E)

// ---------------- scratch ----------------
__device__ __nv_bfloat16 g_rb[TPAD * NS];
__device__ __nv_bfloat16 g_wt[4][NS * NS];          // [n][k]
__device__ __nv_bfloat16 g_q[NH * TPAD * DH];       // [h][t][d]  (pre-scaled by QSCALE)
__device__ __nv_bfloat16 g_k[NH * TPAD * DH];       // [h][t][d]
__device__ __nv_bfloat16 g_vt[NH * DH * TPAD];      // [h][d][t]
__device__ __nv_bfloat16 g_att[TPAD * NS];
__device__ __nv_bfloat16 g_biasb[(size_t)TPAD * TPAD]; // bias * log2e, bf16

// ---------------- helpers ----------------
__device__ __forceinline__ void mma16816(float c[4], const unsigned a[4], const unsigned b[2]) {
    asm volatile(
        "mma.sync.aligned.m16n8k16.row.col.f32.bf16.bf16.f32 "
        "{%0,%1,%2,%3}, {%4,%5,%6,%7}, {%8,%9}, {%0,%1,%2,%3};\n"
        : "+f"(c[0]), "+f"(c[1]), "+f"(c[2]), "+f"(c[3])
        : "r"(a[0]), "r"(a[1]), "r"(a[2]), "r"(a[3]), "r"(b[0]), "r"(b[1]));
}
__device__ __forceinline__ void ldsm4(unsigned r[4], const void* p) {
    unsigned a = (unsigned)__cvta_generic_to_shared(p);
    asm volatile("ldmatrix.sync.aligned.m8n8.x4.shared.b16 {%0,%1,%2,%3}, [%4];\n"
        : "=r"(r[0]), "=r"(r[1]), "=r"(r[2]), "=r"(r[3]) : "r"(a));
}
__device__ __forceinline__ unsigned pack_bf16(float lo, float hi) {
    __nv_bfloat162 h = __floats2bfloat162_rn(lo, hi);
    return *reinterpret_cast<unsigned*>(&h);
}
__device__ __forceinline__ float ex2(float x) {
    float y; asm("ex2.approx.ftz.f32 %0, %1;" : "=f"(y) : "f"(x)); return y;
}
__device__ __forceinline__ void cpa16(void* dst, const void* src) {
    unsigned a = (unsigned)__cvta_generic_to_shared(dst);
    asm volatile("cp.async.cg.shared.global [%0], [%1], 16;\n" :: "r"(a), "l"(src));
}
__device__ __forceinline__ void cp_commit() { asm volatile("cp.async.commit_group;\n" ::); }
__device__ __forceinline__ void cp_wait1()  { asm volatile("cp.async.wait_group 1;\n" ::); }
__device__ __forceinline__ void cp_wait0()  { asm volatile("cp.async.wait_group 0;\n" ::); }

// ---------------- weight transpose (fused) ----------------
__global__ void transpose_w_kernel(const float* __restrict__ Wq, const float* __restrict__ Wk,
                                   const float* __restrict__ Wv, const float* __restrict__ Wc) {
    __shared__ float tile[32][33];
    const float* W = (blockIdx.z == 0) ? Wq : (blockIdx.z == 1) ? Wk : (blockIdx.z == 2) ? Wv : Wc;
    int tx = threadIdx.x, ty = threadIdx.y;
    int bx = blockIdx.x * 32, by = blockIdx.y * 32;
    tile[ty][tx] = W[(size_t)(by + ty) * NS + bx + tx];
    __syncthreads();
    g_wt[blockIdx.z][(size_t)(bx + ty) * NS + by + tx] = __float2bfloat16(tile[tx][ty]);
}

// ---------------- bias fp32 -> bf16 * log2e ----------------
__global__ void biasconv_kernel(const float* __restrict__ bias) {
    size_t i = ((size_t)blockIdx.x * 256 + threadIdx.x) * 4;
    float4 v = *(const float4*)(bias + i);
    __nv_bfloat162* o = (__nv_bfloat162*)(g_biasb + i);
    o[0] = __floats2bfloat162_rn(v.x * LOG2E, v.y * LOG2E);
    o[1] = __floats2bfloat162_rn(v.z * LOG2E, v.w * LOG2E);
}

// ---------------- layernorm ----------------
__global__ void ln_kernel(const float* __restrict__ m,
                          const float* __restrict__ gamma,
                          const float* __restrict__ beta) {
    int row = blockIdx.x;
    int tid = threadIdx.x;
    if (row >= N_CTX) {
        unsigned* dst = (unsigned*)(g_rb + (size_t)row * NS);
        dst[tid] = 0u; dst[tid + 256] = 0u;
        return;
    }
    float4 x = ((const float4*)(m + (size_t)row * NS))[tid];
    float s  = x.x + x.y + x.z + x.w;
    float sq = x.x * x.x + x.y * x.y + x.z * x.z + x.w * x.w;
    #pragma unroll
    for (int o = 16; o > 0; o >>= 1) {
        s  += __shfl_xor_sync(0xffffffffu, s,  o);
        sq += __shfl_xor_sync(0xffffffffu, sq, o);
    }
    __shared__ float redS[8], redQ[8], bcast[2];
    int wid = tid >> 5, ln = tid & 31;
    if (ln == 0) { redS[wid] = s; redQ[wid] = sq; }
    __syncthreads();
    if (tid == 0) {
        float S = 0.f, Q = 0.f;
        #pragma unroll
        for (int i = 0; i < 8; i++) { S += redS[i]; Q += redQ[i]; }
        float mu  = S * (1.0f / NS);
        float var = Q * (1.0f / NS) - mu * mu;
        bcast[0] = mu;
        bcast[1] = rsqrtf(var + 1e-5f);
    }
    __syncthreads();
    float mu = bcast[0], rstd = bcast[1];
    float4 g = ((const float4*)gamma)[tid];
    float4 b = ((const float4*)beta)[tid];
    __nv_bfloat162* out = (__nv_bfloat162*)(g_rb + (size_t)row * NS);
    out[2 * tid]     = __floats2bfloat162_rn((x.x - mu) * rstd * g.x + b.x, (x.y - mu) * rstd * g.y + b.y);
    out[2 * tid + 1] = __floats2bfloat162_rn((x.z - mu) * rstd * g.z + b.z, (x.w - mu) * rstd * g.w + b.w);
}

// ======================= fused QKV GEMM (3-stage, ldmatrix) =======================
__global__ __launch_bounds__(256, 2) void gemm_qkv_kernel(const float* __restrict__ bq,
                                                          const float* __restrict__ bv) {
    constexpr int LDS_ = 40;
    __shared__ __nv_bfloat16 As[3][128 * LDS_];
    __shared__ __nv_bfloat16 Bs[3][128 * LDS_];

    int gn0 = blockIdx.x * 128;
    int mode = gn0 >> 10;
    int n0 = gn0 & 1023;
    int t0 = blockIdx.y * 128;
    const __nv_bfloat16* A  = g_rb;
    const __nv_bfloat16* BT = g_wt[mode];

    int tid = threadIdx.x;
    int wid = tid >> 5, lane = tid & 31, gid = lane >> 2, tig = lane & 3;
    int wm = wid & 1, wn = wid >> 1;
    int lrow = (lane & 7) + ((lane >> 3) & 1) * 8, lkhi = (lane >> 4) & 1;  // a-frag
    int brow = (lane & 7) + ((lane >> 4) & 1) * 8, bkhi = (lane >> 3) & 1;  // b-frag

    float c[4][4][4];
    #pragma unroll
    for (int i = 0; i < 4; i++)
        #pragma unroll
        for (int j = 0; j < 4; j++)
            #pragma unroll
            for (int k = 0; k < 4; k++) c[i][j][k] = 0.f;

    auto issue = [&](int kt) {
        int buf = kt % 3, k0 = kt * 32;
        #pragma unroll
        for (int i = 0; i < 2; i++) {
            int idx = tid + i * 256;
            int row = idx >> 2, cc = idx & 3;
            cpa16(&((uint4*)As[buf])[row * 5 + cc], A  + (size_t)(t0 + row) * NS + k0 + cc * 8);
            cpa16(&((uint4*)Bs[buf])[row * 5 + cc], BT + (size_t)(n0 + row) * NS + k0 + cc * 8);
        }
        cp_commit();
    };

    issue(0); issue(1);
    for (int kt = 0; kt < 32; kt++) {
        if (kt == 31) cp_wait0(); else cp_wait1();
        __syncthreads();
        if (kt < 30) issue(kt + 2);
        int buf = kt % 3;
        #pragma unroll
        for (int ks = 0; ks < 2; ks++) {
            unsigned a[4][4], b[2][4];
            #pragma unroll
            for (int mf = 0; mf < 4; mf++)
                ldsm4(a[mf], As[buf] + (wm * 64 + mf * 16 + lrow) * LDS_ + ks * 16 + lkhi * 8);
            #pragma unroll
            for (int np = 0; np < 2; np++)
                ldsm4(b[np], Bs[buf] + (wn * 32 + np * 16 + brow) * LDS_ + ks * 16 + bkhi * 8);
            #pragma unroll
            for (int mf = 0; mf < 4; mf++)
                #pragma unroll
                for (int nf = 0; nf < 4; nf++)
                    mma16816(c[mf][nf], a[mf], &b[nf >> 1][(nf & 1) * 2]);
        }
    }

    #pragma unroll
    for (int mf = 0; mf < 4; mf++) {
        #pragma unroll
        for (int nf = 0; nf < 4; nf++) {
            int r0 = t0 + wm * 64 + mf * 16 + gid;
            int cn = n0 + wn * 32 + nf * 8 + tig * 2;
            float* cc = c[mf][nf];
            const float* bias = (mode == 0) ? bq : (mode == 2) ? bv : nullptr;
            float b0 = bias ? bias[cn] : 0.f;
            float b1 = bias ? bias[cn + 1] : 0.f;
            float v0 = (r0     < N_CTX) ? cc[0] + b0 : 0.f;
            float v1 = (r0     < N_CTX) ? cc[1] + b1 : 0.f;
            float v2 = (r0 + 8 < N_CTX) ? cc[2] + b0 : 0.f;
            float v3 = (r0 + 8 < N_CTX) ? cc[3] + b1 : 0.f;
            if (mode == 0) { v0 *= QSCALE; v1 *= QSCALE; v2 *= QSCALE; v3 *= QSCALE; }
            int head = cn >> 6, d = cn & 63;
            if (mode == 2) {
                __nv_bfloat16* p0 = g_vt + ((size_t)head * DH + d) * TPAD;
                __nv_bfloat16* p1 = p0 + TPAD;
                p0[r0]     = __float2bfloat16(v0);
                p0[r0 + 8] = __float2bfloat16(v2);
                p1[r0]     = __float2bfloat16(v1);
                p1[r0 + 8] = __float2bfloat16(v3);
            } else {
                __nv_bfloat16* base = (mode == 0 ? g_q : g_k);
                __nv_bfloat16* d0 = base + ((size_t)head * TPAD + r0) * DH + d;
                d0[0] = __float2bfloat16(v0);
                d0[1] = __float2bfloat16(v1);
                __nv_bfloat16* d1 = d0 + 8 * DH;
                d1[0] = __float2bfloat16(v2);
                d1[1] = __float2bfloat16(v3);
            }
        }
    }
}

// ======================= output GEMM (3-stage, ldmatrix) =======================
__global__ __launch_bounds__(256, 2) void gemm_out_kernel(const float* __restrict__ bc,
                                                          const float* __restrict__ madd,
                                                          float* __restrict__ out) {
    constexpr int LDS_ = 40;
    __shared__ __nv_bfloat16 As[3][128 * LDS_];
    __shared__ __nv_bfloat16 Bs[3][128 * LDS_];

    int n0 = blockIdx.x * 128, t0 = blockIdx.y * 128;
    const __nv_bfloat16* A  = g_att;
    const __nv_bfloat16* BT = g_wt[3];

    int tid = threadIdx.x;
    int wid = tid >> 5, lane = tid & 31, gid = lane >> 2, tig = lane & 3;
    int wm = wid & 1, wn = wid >> 1;
    int lrow = (lane & 7) + ((lane >> 3) & 1) * 8, lkhi = (lane >> 4) & 1;
    int brow = (lane & 7) + ((lane >> 4) & 1) * 8, bkhi = (lane >> 3) & 1;

    float c[4][4][4];
    #pragma unroll
    for (int i = 0; i < 4; i++)
        #pragma unroll
        for (int j = 0; j < 4; j++)
            #pragma unroll
            for (int k = 0; k < 4; k++) c[i][j][k] = 0.f;

    auto issue = [&](int kt) {
        int buf = kt % 3, k0 = kt * 32;
        #pragma unroll
        for (int i = 0; i < 2; i++) {
            int idx = tid + i * 256;
            int row = idx >> 2, cc = idx & 3;
            cpa16(&((uint4*)As[buf])[row * 5 + cc], A  + (size_t)(t0 + row) * NS + k0 + cc * 8);
            cpa16(&((uint4*)Bs[buf])[row * 5 + cc], BT + (size_t)(n0 + row) * NS + k0 + cc * 8);
        }
        cp_commit();
    };

    issue(0); issue(1);
    for (int kt = 0; kt < 32; kt++) {
        if (kt == 31) cp_wait0(); else cp_wait1();
        __syncthreads();
        if (kt < 30) issue(kt + 2);
        int buf = kt % 3;
        #pragma unroll
        for (int ks = 0; ks < 2; ks++) {
            unsigned a[4][4], b[2][4];
            #pragma unroll
            for (int mf = 0; mf < 4; mf++)
                ldsm4(a[mf], As[buf] + (wm * 64 + mf * 16 + lrow) * LDS_ + ks * 16 + lkhi * 8);
            #pragma unroll
            for (int np = 0; np < 2; np++)
                ldsm4(b[np], Bs[buf] + (wn * 32 + np * 16 + brow) * LDS_ + ks * 16 + bkhi * 8);
            #pragma unroll
            for (int mf = 0; mf < 4; mf++)
                #pragma unroll
                for (int nf = 0; nf < 4; nf++)
                    mma16816(c[mf][nf], a[mf], &b[nf >> 1][(nf & 1) * 2]);
        }
    }

    #pragma unroll
    for (int mf = 0; mf < 4; mf++) {
        #pragma unroll
        for (int nf = 0; nf < 4; nf++) {
            int r0 = t0 + wm * 64 + mf * 16 + gid;
            int cn = n0 + wn * 32 + nf * 8 + tig * 2;
            float* cc = c[mf][nf];
            if (r0 < N_CTX) {
                out[(size_t)r0 * NS + cn]     = madd[(size_t)r0 * NS + cn]     + cc[0] + bc[cn];
                out[(size_t)r0 * NS + cn + 1] = madd[(size_t)r0 * NS + cn + 1] + cc[1] + bc[cn + 1];
            }
            if (r0 + 8 < N_CTX) {
                out[(size_t)(r0 + 8) * NS + cn]     = madd[(size_t)(r0 + 8) * NS + cn]     + cc[2] + bc[cn];
                out[(size_t)(r0 + 8) * NS + cn + 1] = madd[(size_t)(r0 + 8) * NS + cn + 1] + cc[3] + bc[cn + 1];
            }
        }
    }
}

// ======================= flash attention: 128 q rows x 128 k cols, 3-stage =======================
#define LPK 72
#define LPV 136
#define ATTN_SMEM ((128 * LPK + 3 * 128 * LPK + 3 * 64 * LPV) * 2)   // 125952 B

__global__ __launch_bounds__(256, 1) void attn_kernel() {
    extern __shared__ __nv_bfloat16 sm[];
    __nv_bfloat16* Qs = sm;                       // 128*LPK
    __nv_bfloat16* Ks = Qs + 128 * LPK;           // 3 * 128*LPK
    __nv_bfloat16* Vt = Ks + 3 * 128 * LPK;       // 3 * 64*LPV

    int head = blockIdx.x;
    int q0   = blockIdx.y * 128;
    int tid = threadIdx.x, wid = tid >> 5, lane = tid & 31, gid = lane >> 2, tig = lane & 3;
    int lrow = (lane & 7) + ((lane >> 3) & 1) * 8, lkhi = (lane >> 4) & 1;
    int brow = (lane & 7) + ((lane >> 4) & 1) * 8, bkhi = (lane >> 3) & 1;

    const __nv_bfloat16* gq = g_q  + (size_t)head * TPAD * DH;
    const __nv_bfloat16* gk = g_k  + (size_t)head * TPAD * DH;
    const __nv_bfloat16* gv = g_vt + (size_t)head * DH * TPAD;

    auto issue = [&](int kt) {
        int buf = kt % 3, k0 = kt * 128;
        __nv_bfloat16* kd = Ks + buf * 128 * LPK;
        __nv_bfloat16* vd = Vt + buf * 64 * LPV;
        #pragma unroll
        for (int i = 0; i < 4; i++) {               // K: 128 rows x 8 uint4
            int idx = tid + i * 256;
            int row = idx >> 3, cc = idx & 7;
            cpa16(&((uint4*)kd)[row * 9 + cc], gk + (size_t)(k0 + row) * DH + cc * 8);
        }
        #pragma unroll
        for (int i = 0; i < 4; i++) {               // V: 64 rows x 16 uint4
            int idx = tid + i * 256;
            int row = idx >> 4, cc = idx & 15;
            cpa16(&((uint4*)vd)[row * 17 + cc], gv + (size_t)row * TPAD + k0 + cc * 8);
        }
        cp_commit();
    };

    issue(0); issue(1);
    #pragma unroll
    for (int i = 0; i < 4; i++) {                   // Q: plain loads
        int idx = tid + i * 256;
        int row = idx >> 3, cc = idx & 7;
        ((uint4*)Qs)[row * 9 + cc] = *(const uint4*)(gq + (size_t)(q0 + row) * DH + cc * 8);
    }
    __syncthreads();

    unsigned qa[4][4];                               // Q a-fragments cached for all iters
    #pragma unroll
    for (int ks = 0; ks < 4; ks++)
        ldsm4(qa[ks], Qs + (wid * 16 + lrow) * LPK + ks * 16 + lkhi * 8);

    float oacc[8][4];
    #pragma unroll
    for (int j = 0; j < 8; j++)
        #pragma unroll
        for (int i = 0; i < 4; i++) oacc[j][i] = 0.f;
    float mr0 = -1e30f, mr1 = -1e30f, l0 = 0.f, l1 = 0.f;
    int qrow = q0 + wid * 16 + gid;
    const __nv_bfloat16* bptr0 = g_biasb + (size_t)qrow * TPAD + tig * 2;
    const __nv_bfloat16* bptr1 = bptr0 + 8 * TPAD;

    for (int kt = 0; kt < 32; kt++) {
        int k0 = kt * 128;
        unsigned bb0[16], bb1[16];                   // bias prefetch (L2 hits, hidden by QK mma)
        #pragma unroll
        for (int j = 0; j < 16; j++) {
            bb0[j] = *(const unsigned*)(bptr0 + k0 + j * 8);
            bb1[j] = *(const unsigned*)(bptr1 + k0 + j * 8);
        }
        if (kt == 31) cp_wait0(); else cp_wait1();
        __syncthreads();
        if (kt < 30) issue(kt + 2);
        int buf = kt % 3;
        const __nv_bfloat16* kd = Ks + buf * 128 * LPK;
        const __nv_bfloat16* vd = Vt + buf * 64 * LPV;

        float s[16][4];
        #pragma unroll
        for (int j = 0; j < 16; j++)
            #pragma unroll
            for (int i = 0; i < 4; i++) s[j][i] = 0.f;

        #pragma unroll
        for (int ks = 0; ks < 4; ks++) {
            #pragma unroll
            for (int jp = 0; jp < 8; jp++) {
                unsigned kb[4];
                ldsm4(kb, kd + (jp * 16 + brow) * LPK + ks * 16 + bkhi * 8);
                mma16816(s[2 * jp],     qa[ks], &kb[0]);
                mma16816(s[2 * jp + 1], qa[ks], &kb[2]);
            }
        }

        // logits (log2 domain, q pre-scaled, bias pre-scaled) + online softmax
        float rm0 = -1e30f, rm1 = -1e30f;
        #pragma unroll
        for (int j = 0; j < 16; j++) {
            float2 b0 = __bfloat1622float2(*reinterpret_cast<const __nv_bfloat162*>(&bb0[j]));
            float2 b1 = __bfloat1622float2(*reinterpret_cast<const __nv_bfloat162*>(&bb1[j]));
            s[j][0] += b0.x; s[j][1] += b0.y;
            s[j][2] += b1.x; s[j][3] += b1.y;
            rm0 = fmaxf(rm0, fmaxf(s[j][0], s[j][1]));
            rm1 = fmaxf(rm1, fmaxf(s[j][2], s[j][3]));
        }
        rm0 = fmaxf(rm0, __shfl_xor_sync(0xffffffffu, rm0, 1));
        rm0 = fmaxf(rm0, __shfl_xor_sync(0xffffffffu, rm0, 2));
        rm1 = fmaxf(rm1, __shfl_xor_sync(0xffffffffu, rm1, 1));
        rm1 = fmaxf(rm1, __shfl_xor_sync(0xffffffffu, rm1, 2));
        float mn0 = fmaxf(mr0, rm0), mn1 = fmaxf(mr1, rm1);
        float al0 = ex2(mr0 - mn0), al1 = ex2(mr1 - mn1);

        float rs0 = 0.f, rs1 = 0.f;
        #pragma unroll
        for (int j = 0; j < 16; j++) {
            s[j][0] = ex2(s[j][0] - mn0);
            s[j][1] = ex2(s[j][1] - mn0);
            s[j][2] = ex2(s[j][2] - mn1);
            s[j][3] = ex2(s[j][3] - mn1);
            rs0 += s[j][0] + s[j][1];
            rs1 += s[j][2] + s[j][3];
        }
        l0 = l0 * al0 + rs0;       // per-thread partial; lane-group reduce deferred to end
        l1 = l1 * al1 + rs1;
        mr0 = mn0; mr1 = mn1;
        #pragma unroll
        for (int j = 0; j < 8; j++) {
            oacc[j][0] *= al0; oacc[j][1] *= al0;
            oacc[j][2] *= al1; oacc[j][3] *= al1;
        }

        // O += P @ V
        #pragma unroll
        for (int kk = 0; kk < 8; kk++) {
            unsigned a[4];
            a[0] = pack_bf16(s[2 * kk][0],     s[2 * kk][1]);
            a[1] = pack_bf16(s[2 * kk][2],     s[2 * kk][3]);
            a[2] = pack_bf16(s[2 * kk + 1][0], s[2 * kk + 1][1]);
            a[3] = pack_bf16(s[2 * kk + 1][2], s[2 * kk + 1][3]);
            #pragma unroll
            for (int jp = 0; jp < 4; jp++) {
                unsigned vb[4];
                ldsm4(vb, vd + (jp * 16 + brow) * LPV + kk * 16 + bkhi * 8);
                mma16816(oacc[2 * jp],     a, &vb[0]);
                mma16816(oacc[2 * jp + 1], a, &vb[2]);
            }
        }
    }

    l0 += __shfl_xor_sync(0xffffffffu, l0, 1);
    l0 += __shfl_xor_sync(0xffffffffu, l0, 2);
    l1 += __shfl_xor_sync(0xffffffffu, l1, 1);
    l1 += __shfl_xor_sync(0xffffffffu, l1, 2);
    float inv0 = 1.f / l0, inv1 = 1.f / l1;
    #pragma unroll
    for (int j = 0; j < 8; j++) {
        int col = head * DH + j * 8 + tig * 2;
        __nv_bfloat16* d0 = g_att + (size_t)qrow * NS + col;
        __nv_bfloat16* d1 = g_att + (size_t)(qrow + 8) * NS + col;
        d0[0] = __float2bfloat16(oacc[j][0] * inv0);
        d0[1] = __float2bfloat16(oacc[j][1] * inv0);
        d1[0] = __float2bfloat16(oacc[j][2] * inv1);
        d1[1] = __float2bfloat16(oacc[j][3] * inv1);
    }
}

// ---------------- launch ----------------
extern "C" void kernel_launch(void* const* d_in, const int* in_sizes, int n_in,
                              void* d_out, int out_size) {
    const float* m     = (const float*)d_in[0];
    const float* bias  = (const float*)d_in[1];
    const float* gamma = (const float*)d_in[2];
    const float* beta  = (const float*)d_in[3];
    const float* Wq    = (const float*)d_in[4];
    const float* bq    = (const float*)d_in[5];
    const float* Wk    = (const float*)d_in[6];
    const float* Wv    = (const float*)d_in[7];
    const float* bv    = (const float*)d_in[8];
    const float* Wc    = (const float*)d_in[9];
    const float* bc    = (const float*)d_in[10];
    float* out = (float*)d_out;

    transpose_w_kernel<<<dim3(32, 32, 4), dim3(32, 32)>>>(Wq, Wk, Wv, Wc);
    biasconv_kernel<<<(TPAD * TPAD) / (256 * 4), 256>>>(bias);
    ln_kernel<<<TPAD, 256>>>(m, gamma, beta);

    gemm_qkv_kernel<<<dim3(24, 32), 256>>>(bq, bv);

    cudaFuncSetAttribute(attn_kernel, cudaFuncAttributeMaxDynamicSharedMemorySize, ATTN_SMEM);
    attn_kernel<<<dim3(NH, TPAD / 128), 256, ATTN_SMEM>>>();

    gemm_out_kernel<<<dim3(8, 32), 256>>>(bc, m, out);
}